// round 12
// baseline (speedup 1.0000x reference)
#include <cuda_runtime.h>

#define NN 50000
#define EE 800000
#define HH 128
#define CUTOFF_V 10.0f

// ---------------- device scratch (no allocations allowed) ----------------
__device__ float g_W[(size_t)EE * HH];     // edge gate rows (only active rows valid)
__device__ float g_hA[NN * HH];
__device__ float g_hB[NN * HH];
__device__ float g_agg[NN * HH];
__device__ int g_active[EE];
__device__ unsigned char g_mask[EE];
__device__ int g_count;

// ---------------- f32x2 packed-FMA helpers (Blackwell) ----------------
__device__ __forceinline__ void fma2(unsigned long long& d, unsigned long long a, unsigned long long b) {
    asm("fma.rn.f32x2 %0, %1, %2, %0;" : "+l"(d) : "l"(a), "l"(b));
}
__device__ __forceinline__ float2 up2(unsigned long long v) {
    float2 f;
    asm("mov.b64 {%0, %1}, %2;" : "=f"(f.x), "=f"(f.y) : "l"(v));
    return f;
}

// Weight layout: src row-major [128 k][128 c] ->
//   word(k,c) = (k>>1)*256 + (c>>3)*16 + (c&7)*2 + (k&1)
// K-pairs interleaved; per (kp, colgroup) the 8 columns' (even,odd) pairs are
// 16 contiguous floats -> a thread's B loads are 4x LDS.128 per kp, with only
// 16 distinct addresses per warp (2-way replicated) = conflict-free.
__device__ __forceinline__ void fill_wp(float* __restrict__ dst, const float* __restrict__ src,
                                        int tid, int nthr) {
    for (int i = tid; i < 4096; i += nthr) {
        int k = i >> 5, c4 = (i & 31) * 4;
        float4 w = reinterpret_cast<const float4*>(src)[i];
        int base = (k >> 1) * 256 + (k & 1);
        dst[base + ((c4 + 0) >> 3) * 16 + ((c4 + 0) & 7) * 2] = w.x;
        dst[base + ((c4 + 1) >> 3) * 16 + ((c4 + 1) & 7) * 2] = w.y;
        dst[base + ((c4 + 2) >> 3) * 16 + ((c4 + 2) & 7) * 2] = w.z;
        dst[base + ((c4 + 3) >> 3) * 16 + ((c4 + 3) & 7) * 2] = w.w;
    }
}

// 128x128 @ 128x128 GEMM, 256 threads, thread tile 8 rows x 8 cols, K-paired f32x2.
// rg = tid>>4 (16 rowgroups of 8 rows), cgrp = tid&15 (8 cols each).
// acc[i][c] = (even-k, odd-k) partial sums for row rg*8+i, col cgrp*8+c.
__device__ __forceinline__ void gemm88(const float* __restrict__ sA,
                                       const float* __restrict__ sWp,
                                       int rg, int cgrp, unsigned long long acc[8][8]) {
    const float* a0 = sA + rg * (8 * 128);
    const float* w0 = sWp + cgrp * 16;
#pragma unroll 1
    for (int kp = 0; kp < 64; kp += 2) {   // body = 2 k-pairs = 4 k
        const float* wb = w0 + kp * 256;
        ulonglong2 b00 = *reinterpret_cast<const ulonglong2*>(wb);        // kp:   cols 0,1
        ulonglong2 b01 = *reinterpret_cast<const ulonglong2*>(wb + 4);    // kp:   cols 2,3
        ulonglong2 b02 = *reinterpret_cast<const ulonglong2*>(wb + 8);    // kp:   cols 4,5
        ulonglong2 b03 = *reinterpret_cast<const ulonglong2*>(wb + 12);   // kp:   cols 6,7
        ulonglong2 b10 = *reinterpret_cast<const ulonglong2*>(wb + 256);  // kp+1: cols 0,1
        ulonglong2 b11 = *reinterpret_cast<const ulonglong2*>(wb + 260);
        ulonglong2 b12 = *reinterpret_cast<const ulonglong2*>(wb + 264);
        ulonglong2 b13 = *reinterpret_cast<const ulonglong2*>(wb + 268);
        const int k = kp * 2;
#pragma unroll
        for (int i = 0; i < 8; ++i) {
            ulonglong2 ap = *reinterpret_cast<const ulonglong2*>(a0 + i * 128 + k);  // a[k..k+3]
            fma2(acc[i][0], ap.x, b00.x); fma2(acc[i][1], ap.x, b00.y);
            fma2(acc[i][2], ap.x, b01.x); fma2(acc[i][3], ap.x, b01.y);
            fma2(acc[i][4], ap.x, b02.x); fma2(acc[i][5], ap.x, b02.y);
            fma2(acc[i][6], ap.x, b03.x); fma2(acc[i][7], ap.x, b03.y);
            fma2(acc[i][0], ap.y, b10.x); fma2(acc[i][1], ap.y, b10.y);
            fma2(acc[i][2], ap.y, b11.x); fma2(acc[i][3], ap.y, b11.y);
            fma2(acc[i][4], ap.y, b12.x); fma2(acc[i][5], ap.y, b12.y);
            fma2(acc[i][6], ap.y, b13.x); fma2(acc[i][7], ap.y, b13.y);
        }
    }
}

// ---------------- small kernels ----------------
__global__ void k_init() { g_count = 0; }

// mask + warp-aggregated compaction of active edges (E divisible by 256)
__global__ void __launch_bounds__(256) k_compact(const float* __restrict__ elen) {
    int e = blockIdx.x * 256 + threadIdx.x;
    int lane = threadIdx.x & 31;
    bool a = (elen[e] <= CUTOFF_V);
    g_mask[e] = a ? (unsigned char)1 : (unsigned char)0;
    unsigned m = __ballot_sync(0xffffffffu, a);
    int cnt = __popc(m);
    int base = 0;
    if (lane == 0 && cnt) base = atomicAdd(&g_count, cnt);
    base = __shfl_sync(0xffffffffu, base, 0);
    if (a) {
        int off = __popc(m & ((1u << lane) - 1u));
        g_active[base + off] = e;
    }
}

__global__ void __launch_bounds__(256) k_zero_agg() {
    int i = blockIdx.x * 256 + threadIdx.x;  // exactly N*H/4 threads
    reinterpret_cast<float4*>(g_agg)[i] = make_float4(0.f, 0.f, 0.f, 0.f);
}

// message + scatter-add: one warp per edge, 4 floats per lane.
__global__ void __launch_bounds__(256) k_message(const int* __restrict__ ei,
                                                 const float* __restrict__ hin) {
    int idx = blockIdx.x * 256 + threadIdx.x;  // exactly E*32 threads
    int e = idx >> 5;
    int c4 = idx & 31;
    int s = __ldg(ei + e);
    float4 m = __ldg(reinterpret_cast<const float4*>(hin) + s * 32 + c4);
    if (g_mask[e]) {
        float4 wv = __ldcs(reinterpret_cast<const float4*>(g_W + (size_t)e * HH) + c4);
        m.x += wv.x; m.y += wv.y; m.z += wv.z; m.w += wv.w;
    }
    m.x = fmaxf(m.x, 0.f); m.y = fmaxf(m.y, 0.f);
    m.z = fmaxf(m.z, 0.f); m.w = fmaxf(m.w, 0.f);
    int d = __ldg(ei + EE + e);
    float* ap = g_agg + (size_t)d * HH + c4 * 4;
    asm volatile("red.global.add.v4.f32 [%0], {%1,%2,%3,%4};"
                 :: "l"(ap), "f"(m.x), "f"(m.y), "f"(m.z), "f"(m.w) : "memory");
}

// ---------------- fused 2-layer MLP: 256 threads, 128-row tiles, 8x8 tile ----------------
// sIn (64 KB) is reused in-place for the hidden tile (hid held in regs between).
// MODE 0: edge gate  : rows = g_count (compacted), in = edge_attr[g_active[r]], out = g_W[e]
// MODE 1: node update: in = g_agg + hin, out = relu(mlp(in)) + hin
// MODE 2: node update: in = g_agg + hin, out = mlp(in) + hin   (last conv)
template <int MODE>
__global__ void __launch_bounds__(256, 1) k_mlp2(const float* __restrict__ inp,
                                                 const float* __restrict__ hin,
                                                 const float* __restrict__ wa,
                                                 const float* __restrict__ ba,
                                                 const float* __restrict__ wb,
                                                 const float* __restrict__ bb,
                                                 float* __restrict__ hout) {
    extern __shared__ float sm[];
    float* sWa = sm;            // 16384 floats (pair-permuted)
    float* sWb = sm + 16384;    // 16384 (pair-permuted)
    float* sIn = sm + 32768;    // 16384 (row-major 128x128; doubles as hidden tile)
    // total = 49152 floats = 196608 bytes

    fill_wp(sWa, wa, threadIdx.x, 256);
    fill_wp(sWb, wb, threadIdx.x, 256);
    __syncthreads();

    const int rows = (MODE == 0) ? g_count : NN;
    const int ntiles = (rows + 127) >> 7;
    const int rg = threadIdx.x >> 4;      // 0..15: rows rg*8..rg*8+7
    const int cgrp = threadIdx.x & 15;    // cols cgrp*8..cgrp*8+7
    const float4 ba0 = reinterpret_cast<const float4*>(ba)[cgrp * 2];
    const float4 ba1 = reinterpret_cast<const float4*>(ba)[cgrp * 2 + 1];
    const float4 bb0 = reinterpret_cast<const float4*>(bb)[cgrp * 2];
    const float4 bb1 = reinterpret_cast<const float4*>(bb)[cgrp * 2 + 1];

    for (int t = blockIdx.x; t < ntiles; t += gridDim.x) {
        const int base = t << 7;
        // load 128x128 input tile
        for (int i = threadIdx.x; i < 4096; i += 256) {
            int r = i >> 5, c4 = i & 31;
            int gr = base + r;
            float4 v = make_float4(0.f, 0.f, 0.f, 0.f);
            if (gr < rows) {
                if constexpr (MODE == 0) {
                    int e = g_active[gr];
                    v = __ldcs(reinterpret_cast<const float4*>(inp + (size_t)e * HH) + c4);
                } else {
                    float4 x = reinterpret_cast<const float4*>(g_agg)[gr * 32 + c4];
                    float4 y = __ldg(reinterpret_cast<const float4*>(hin) + gr * 32 + c4);
                    v = make_float4(x.x + y.x, x.y + y.y, x.z + y.z, x.w + y.w);
                }
            }
            reinterpret_cast<float4*>(sIn)[i] = v;
        }
        __syncthreads();  // S1: sIn ready

        unsigned long long acc[8][8];
#pragma unroll
        for (int i = 0; i < 8; ++i)
#pragma unroll
            for (int c = 0; c < 8; ++c) acc[i][c] = 0ULL;
        gemm88(sIn, sWa, rg, cgrp, acc);

        // hidden tile in registers: relu(acc.lo+acc.hi+bias)
        float4 hid[8][2];
#pragma unroll
        for (int i = 0; i < 8; ++i) {
            float2 p0 = up2(acc[i][0]), p1 = up2(acc[i][1]), p2 = up2(acc[i][2]), p3 = up2(acc[i][3]);
            float2 p4 = up2(acc[i][4]), p5 = up2(acc[i][5]), p6 = up2(acc[i][6]), p7 = up2(acc[i][7]);
            hid[i][0] = make_float4(fmaxf(p0.x + p0.y + ba0.x, 0.f), fmaxf(p1.x + p1.y + ba0.y, 0.f),
                                    fmaxf(p2.x + p2.y + ba0.z, 0.f), fmaxf(p3.x + p3.y + ba0.w, 0.f));
            hid[i][1] = make_float4(fmaxf(p4.x + p4.y + ba1.x, 0.f), fmaxf(p5.x + p5.y + ba1.y, 0.f),
                                    fmaxf(p6.x + p6.y + ba1.z, 0.f), fmaxf(p7.x + p7.y + ba1.w, 0.f));
        }
        __syncthreads();  // S2: all gemm1 reads of sIn complete

        // store hidden tile into sIn (in-place)
#pragma unroll
        for (int i = 0; i < 8; ++i) {
            float4* row = reinterpret_cast<float4*>(sIn + (rg * 8 + i) * 128);
            row[cgrp * 2] = hid[i][0];
            row[cgrp * 2 + 1] = hid[i][1];
        }
        __syncthreads();  // S3: hidden tile visible

#pragma unroll
        for (int i = 0; i < 8; ++i)
#pragma unroll
            for (int c = 0; c < 8; ++c) acc[i][c] = 0ULL;
        gemm88(sIn, sWb, rg, cgrp, acc);

#pragma unroll
        for (int i = 0; i < 8; ++i) {
            int gr = base + rg * 8 + i;
            if (gr < rows) {
                float2 p0 = up2(acc[i][0]), p1 = up2(acc[i][1]), p2 = up2(acc[i][2]), p3 = up2(acc[i][3]);
                float2 p4 = up2(acc[i][4]), p5 = up2(acc[i][5]), p6 = up2(acc[i][6]), p7 = up2(acc[i][7]);
                float4 v0 = make_float4(p0.x + p0.y + bb0.x, p1.x + p1.y + bb0.y,
                                        p2.x + p2.y + bb0.z, p3.x + p3.y + bb0.w);
                float4 v1 = make_float4(p4.x + p4.y + bb1.x, p5.x + p5.y + bb1.y,
                                        p6.x + p6.y + bb1.z, p7.x + p7.y + bb1.w);
                if constexpr (MODE == 0) {
                    int e = g_active[gr];
                    float4* dst = reinterpret_cast<float4*>(g_W + (size_t)e * HH);
                    __stcs(dst + cgrp * 2, v0);
                    __stcs(dst + cgrp * 2 + 1, v1);
                } else {
                    if constexpr (MODE == 1) {
                        v0.x = fmaxf(v0.x, 0.f); v0.y = fmaxf(v0.y, 0.f);
                        v0.z = fmaxf(v0.z, 0.f); v0.w = fmaxf(v0.w, 0.f);
                        v1.x = fmaxf(v1.x, 0.f); v1.y = fmaxf(v1.y, 0.f);
                        v1.z = fmaxf(v1.z, 0.f); v1.w = fmaxf(v1.w, 0.f);
                    }
                    float4 h0 = __ldg(reinterpret_cast<const float4*>(hin) + gr * 32 + cgrp * 2);
                    float4 h1 = __ldg(reinterpret_cast<const float4*>(hin) + gr * 32 + cgrp * 2 + 1);
                    v0.x += h0.x; v0.y += h0.y; v0.z += h0.z; v0.w += h0.w;
                    v1.x += h1.x; v1.y += h1.y; v1.z += h1.z; v1.w += h1.w;
                    reinterpret_cast<float4*>(hout)[gr * 32 + cgrp * 2] = v0;
                    reinterpret_cast<float4*>(hout)[gr * 32 + cgrp * 2 + 1] = v1;
                }
            }
        }
        __syncthreads();  // S4: gemm2 reads done before next tile's load overwrites sIn
    }
}

// ---------------- node embedding: x = relu(z@w0a+b0a)@w0b+b0b (K1=5) ----------------
// smem: sWb 16384 + sHid 16384 + sWa 640 = 33408 floats = 133632 bytes
#define NODE_EMB_SMEM 133632
__global__ void __launch_bounds__(256, 1) k_node_emb(const float* __restrict__ z,
                                                     const float* __restrict__ w0a,
                                                     const float* __restrict__ b0a,
                                                     const float* __restrict__ w0b,
                                                     const float* __restrict__ b0b) {
    extern __shared__ float sm[];
    float* sWb = sm;            // 16384 (pair-permuted)
    float* sHid = sm + 16384;   // 16384 (128x128)
    float* sWa = sm + 32768;    // 640
    fill_wp(sWb, w0b, threadIdx.x, 256);
    for (int i = threadIdx.x; i < 640; i += 256) sWa[i] = w0a[i];
    __syncthreads();

    const int rg = threadIdx.x >> 4;
    const int cgrp = threadIdx.x & 15;
    const float4 bb0 = reinterpret_cast<const float4*>(b0b)[cgrp * 2];
    const float4 bb1 = reinterpret_cast<const float4*>(b0b)[cgrp * 2 + 1];
    const int ntiles = (NN + 127) >> 7;
    for (int t = blockIdx.x; t < ntiles; t += gridDim.x) {
        int base = t << 7;
        for (int i = threadIdx.x; i < 16384; i += 256) {
            int r = i >> 7, c = i & 127;
            int gr = base + r;
            float acc = 0.f;
            if (gr < NN) {
#pragma unroll
                for (int k = 0; k < 5; ++k)
                    acc = fmaf(__ldg(z + gr * 5 + k), sWa[k * 128 + c], acc);
                acc = fmaxf(acc + __ldg(b0a + c), 0.f);
            }
            sHid[i] = acc;
        }
        __syncthreads();
        unsigned long long acc[8][8];
#pragma unroll
        for (int i = 0; i < 8; ++i)
#pragma unroll
            for (int c = 0; c < 8; ++c) acc[i][c] = 0ULL;
        gemm88(sHid, sWb, rg, cgrp, acc);
#pragma unroll
        for (int i = 0; i < 8; ++i) {
            int gr = base + rg * 8 + i;
            if (gr < NN) {
                float2 p0 = up2(acc[i][0]), p1 = up2(acc[i][1]), p2 = up2(acc[i][2]), p3 = up2(acc[i][3]);
                float2 p4 = up2(acc[i][4]), p5 = up2(acc[i][5]), p6 = up2(acc[i][6]), p7 = up2(acc[i][7]);
                float4 v0 = make_float4(p0.x + p0.y + bb0.x, p1.x + p1.y + bb0.y,
                                        p2.x + p2.y + bb0.z, p3.x + p3.y + bb0.w);
                float4 v1 = make_float4(p4.x + p4.y + bb1.x, p5.x + p5.y + bb1.y,
                                        p6.x + p6.y + bb1.z, p7.x + p7.y + bb1.w);
                reinterpret_cast<float4*>(g_hA)[gr * 32 + cgrp * 2] = v0;
                reinterpret_cast<float4*>(g_hA)[gr * 32 + cgrp * 2 + 1] = v1;
            }
        }
        __syncthreads();  // sHid reuse guard
    }
}

// ---------------- launch ----------------
extern "C" void kernel_launch(void* const* d_in, const int* in_sizes, int n_in,
                              void* d_out, int out_size) {
    const float* z    = (const float*)d_in[0];
    const int*   ei   = (const int*)d_in[1];
    const float* eatt = (const float*)d_in[2];
    const float* elen = (const float*)d_in[3];
    const float* w0a  = (const float*)d_in[4];
    const float* b0a  = (const float*)d_in[5];
    const float* w0b  = (const float*)d_in[6];
    const float* b0b  = (const float*)d_in[7];
    const float* w1a  = (const float*)d_in[8];
    const float* b1a  = (const float*)d_in[9];
    const float* w1b  = (const float*)d_in[10];
    const float* b1b  = (const float*)d_in[11];
    const float* w2a  = (const float*)d_in[12];
    const float* b2a  = (const float*)d_in[13];
    const float* w2b  = (const float*)d_in[14];
    const float* b2b  = (const float*)d_in[15];
    float* out = (float*)d_out;

    cudaFuncSetAttribute(k_mlp2<0>, cudaFuncAttributeMaxDynamicSharedMemorySize, 196608);
    cudaFuncSetAttribute(k_mlp2<1>, cudaFuncAttributeMaxDynamicSharedMemorySize, 196608);
    cudaFuncSetAttribute(k_mlp2<2>, cudaFuncAttributeMaxDynamicSharedMemorySize, 196608);
    cudaFuncSetAttribute(k_node_emb, cudaFuncAttributeMaxDynamicSharedMemorySize, NODE_EMB_SMEM);

    float *hA, *hB;
    cudaGetSymbolAddress((void**)&hA, g_hA);
    cudaGetSymbolAddress((void**)&hB, g_hB);

    const int ZERO_BLOCKS = (NN * HH / 4) / 256;  // 6250
    const int MSG_BLOCKS  = (EE * 32) / 256;      // 100000

    k_init<<<1, 1>>>();
    k_compact<<<EE / 256, 256>>>(elen);
    k_node_emb<<<148, 256, NODE_EMB_SMEM>>>(z, w0a, b0a, w0b, b0b);
    k_mlp2<0><<<148, 256, 196608>>>(eatt, nullptr, w2a, b2a, w2b, b2b, nullptr);

    // conv 0: hA -> hB
    k_zero_agg<<<ZERO_BLOCKS, 256>>>();
    k_message<<<MSG_BLOCKS, 256>>>(ei, hA);
    k_mlp2<1><<<148, 256, 196608>>>(nullptr, hA, w1a, b1a, w1b, b1b, hB);

    // conv 1: hB -> hA
    k_zero_agg<<<ZERO_BLOCKS, 256>>>();
    k_message<<<MSG_BLOCKS, 256>>>(ei, hB);
    k_mlp2<1><<<148, 256, 196608>>>(nullptr, hB, w1a, b1a, w1b, b1b, hA);

    // conv 2: hA -> out (no inter-layer relu)
    k_zero_agg<<<ZERO_BLOCKS, 256>>>();
    k_message<<<MSG_BLOCKS, 256>>>(ei, hA);
    k_mlp2<2><<<148, 256, 196608>>>(nullptr, hA, w1a, b1a, w1b, b1b, out);
}

// round 13
// speedup vs baseline: 1.3950x; 1.3950x over previous
#include <cuda_runtime.h>

#define NN 50000
#define EE 800000
#define HH 128
#define CUTOFF_V 10.0f
#define TM 96   // rows per MLP tile

// ---------------- device scratch (no allocations allowed) ----------------
__device__ float g_W[(size_t)EE * HH];     // edge gate rows (only active rows valid)
__device__ float g_hA[NN * HH];
__device__ float g_hB[NN * HH];
__device__ float g_agg[NN * HH];
__device__ int g_active[EE];
__device__ unsigned char g_mask[EE];
__device__ int g_count;

// ---------------- f32x2 packed-FMA helpers (Blackwell) ----------------
__device__ __forceinline__ void fma2(unsigned long long& d, unsigned long long a, unsigned long long b) {
    asm("fma.rn.f32x2 %0, %1, %2, %0;" : "+l"(d) : "l"(a), "l"(b));
}
__device__ __forceinline__ float2 up2(unsigned long long v) {
    float2 f;
    asm("mov.b64 {%0, %1}, %2;" : "=f"(f.x), "=f"(f.y) : "l"(v));
    return f;
}

// j-split weight layout: src row-major [128 k][128 c] ->
//   word(k,c) = (k>>1)*256 + ((c>>1)&3)*64 + (c>>3)*4 + (c&1)*2 + (k&1)
// For each (kp, j) the 16 colgroups' 16B fragments are CONTIGUOUS (16B stride,
// 256B span) -> each warp B-load = 2 conflict-free wavefronts. A fragment word
// pair (m*2 + parity) = (w[2kp][c], w[2kp+1][c]) = one f32x2 B operand.
__device__ __forceinline__ void fill_wp(float* __restrict__ dst, const float* __restrict__ src,
                                        int tid, int nthr) {
    for (int i = tid; i < 4096; i += nthr) {
        int k = i >> 5, c4 = (i & 31) * 4;
        float4 w = reinterpret_cast<const float4*>(src)[i];
        int kb = (k >> 1) * 256 + (k & 1);
#pragma unroll
        for (int j = 0; j < 4; ++j) {
            int c = c4 + j;
            float val = (j == 0) ? w.x : (j == 1) ? w.y : (j == 2) ? w.z : w.w;
            dst[kb + ((c >> 1) & 3) * 64 + (c >> 3) * 4 + (c & 1) * 2] = val;
        }
    }
}

// 96x128 @ 128x128 GEMM, 256 threads, thread tile 6 rows x 8 cols, K-paired f32x2.
// rg = tid>>4 (16 rowgroups of 6 rows), cgrp = tid&15 (8 cols each).
__device__ __forceinline__ void gemm96(const float* __restrict__ sA,
                                       const float* __restrict__ sWp,
                                       int rg, int cgrp, unsigned long long acc[6][8]) {
    const float* a0 = sA + rg * (6 * 128);
    const float* w0 = sWp + cgrp * 4;
#pragma unroll 1
    for (int kp = 0; kp < 64; kp += 2) {   // body = 2 k-pairs = 4 k
        const float* wb = w0 + kp * 256;
        ulonglong2 b00 = *reinterpret_cast<const ulonglong2*>(wb);        // kp:   cols 0,1
        ulonglong2 b01 = *reinterpret_cast<const ulonglong2*>(wb + 64);   // kp:   cols 2,3
        ulonglong2 b02 = *reinterpret_cast<const ulonglong2*>(wb + 128);  // kp:   cols 4,5
        ulonglong2 b03 = *reinterpret_cast<const ulonglong2*>(wb + 192);  // kp:   cols 6,7
        ulonglong2 b10 = *reinterpret_cast<const ulonglong2*>(wb + 256);  // kp+1
        ulonglong2 b11 = *reinterpret_cast<const ulonglong2*>(wb + 320);
        ulonglong2 b12 = *reinterpret_cast<const ulonglong2*>(wb + 384);
        ulonglong2 b13 = *reinterpret_cast<const ulonglong2*>(wb + 448);
#pragma unroll
        for (int i = 0; i < 6; ++i) {
            ulonglong2 ap = *reinterpret_cast<const ulonglong2*>(a0 + i * 128 + kp * 2);
            fma2(acc[i][0], ap.x, b00.x); fma2(acc[i][1], ap.x, b00.y);
            fma2(acc[i][2], ap.x, b01.x); fma2(acc[i][3], ap.x, b01.y);
            fma2(acc[i][4], ap.x, b02.x); fma2(acc[i][5], ap.x, b02.y);
            fma2(acc[i][6], ap.x, b03.x); fma2(acc[i][7], ap.x, b03.y);
            fma2(acc[i][0], ap.y, b10.x); fma2(acc[i][1], ap.y, b10.y);
            fma2(acc[i][2], ap.y, b11.x); fma2(acc[i][3], ap.y, b11.y);
            fma2(acc[i][4], ap.y, b12.x); fma2(acc[i][5], ap.y, b12.y);
            fma2(acc[i][6], ap.y, b13.x); fma2(acc[i][7], ap.y, b13.y);
        }
    }
}

// ---------------- small kernels ----------------
__global__ void k_init() { g_count = 0; }

__global__ void __launch_bounds__(256) k_compact(const float* __restrict__ elen) {
    int e = blockIdx.x * 256 + threadIdx.x;
    int lane = threadIdx.x & 31;
    bool a = (elen[e] <= CUTOFF_V);
    g_mask[e] = a ? (unsigned char)1 : (unsigned char)0;
    unsigned m = __ballot_sync(0xffffffffu, a);
    int cnt = __popc(m);
    int base = 0;
    if (lane == 0 && cnt) base = atomicAdd(&g_count, cnt);
    base = __shfl_sync(0xffffffffu, base, 0);
    if (a) {
        int off = __popc(m & ((1u << lane) - 1u));
        g_active[base + off] = e;
    }
}

__global__ void __launch_bounds__(256) k_zero_agg() {
    int i = blockIdx.x * 256 + threadIdx.x;  // exactly N*H/4 threads
    reinterpret_cast<float4*>(g_agg)[i] = make_float4(0.f, 0.f, 0.f, 0.f);
}

// message + scatter-add: one warp per edge, 4 floats per lane.
__global__ void __launch_bounds__(256) k_message(const int* __restrict__ ei,
                                                 const float* __restrict__ hin) {
    int idx = blockIdx.x * 256 + threadIdx.x;  // exactly E*32 threads
    int e = idx >> 5;
    int c4 = idx & 31;
    int s = __ldg(ei + e);
    float4 m = __ldg(reinterpret_cast<const float4*>(hin) + s * 32 + c4);
    if (g_mask[e]) {
        float4 wv = __ldcs(reinterpret_cast<const float4*>(g_W + (size_t)e * HH) + c4);
        m.x += wv.x; m.y += wv.y; m.z += wv.z; m.w += wv.w;
    }
    m.x = fmaxf(m.x, 0.f); m.y = fmaxf(m.y, 0.f);
    m.z = fmaxf(m.z, 0.f); m.w = fmaxf(m.w, 0.f);
    int d = __ldg(ei + EE + e);
    float* ap = g_agg + (size_t)d * HH + c4 * 4;
    asm volatile("red.global.add.v4.f32 [%0], {%1,%2,%3,%4};"
                 :: "l"(ap), "f"(m.x), "f"(m.y), "f"(m.z), "f"(m.w) : "memory");
}

// ---------------- fused 2-layer MLP: 256 threads, 96-row tiles, 6x8 tile ----------------
// smem: sWa 16384 + sWb 16384 + sIn 12288 + sHid 12288 = 57344 floats = 229376 B
#define MLP_SMEM 229376
// MODE 0: edge gate  : rows = g_count (compacted), in = edge_attr[g_active[r]], out = g_W[e]
// MODE 1: node update: in = g_agg + hin, out = relu(mlp(in)) + hin
// MODE 2: node update: in = g_agg + hin, out = mlp(in) + hin   (last conv)
template <int MODE>
__global__ void __launch_bounds__(256, 1) k_mlp2(const float* __restrict__ inp,
                                                 const float* __restrict__ hin,
                                                 const float* __restrict__ wa,
                                                 const float* __restrict__ ba,
                                                 const float* __restrict__ wb,
                                                 const float* __restrict__ bb,
                                                 float* __restrict__ hout) {
    extern __shared__ float sm[];
    float* sWa = sm;             // 16384 (j-split)
    float* sWb = sm + 16384;     // 16384 (j-split)
    float* sIn = sm + 32768;     // 12288 (row-major 96x128)
    float* sHid = sm + 45056;    // 12288 (row-major 96x128)

    fill_wp(sWa, wa, threadIdx.x, 256);
    fill_wp(sWb, wb, threadIdx.x, 256);
    __syncthreads();

    const int rows = (MODE == 0) ? g_count : NN;
    const int ntiles = (rows + TM - 1) / TM;
    const int rg = threadIdx.x >> 4;      // 0..15: rows rg*6..rg*6+5
    const int cgrp = threadIdx.x & 15;    // cols cgrp*8..cgrp*8+7
    const float4 ba0 = reinterpret_cast<const float4*>(ba)[cgrp * 2];
    const float4 ba1 = reinterpret_cast<const float4*>(ba)[cgrp * 2 + 1];
    const float4 bb0 = reinterpret_cast<const float4*>(bb)[cgrp * 2];
    const float4 bb1 = reinterpret_cast<const float4*>(bb)[cgrp * 2 + 1];

    for (int t = blockIdx.x; t < ntiles; t += gridDim.x) {
        const int base = t * TM;
        // load 96x128 input tile (3072 float4)
        for (int i = threadIdx.x; i < 3072; i += 256) {
            int r = i >> 5, c4 = i & 31;
            int gr = base + r;
            float4 v = make_float4(0.f, 0.f, 0.f, 0.f);
            if (gr < rows) {
                if constexpr (MODE == 0) {
                    int e = g_active[gr];
                    v = __ldcs(reinterpret_cast<const float4*>(inp + (size_t)e * HH) + c4);
                } else {
                    float4 x = reinterpret_cast<const float4*>(g_agg)[gr * 32 + c4];
                    float4 y = __ldg(reinterpret_cast<const float4*>(hin) + gr * 32 + c4);
                    v = make_float4(x.x + y.x, x.y + y.y, x.z + y.z, x.w + y.w);
                }
            }
            reinterpret_cast<float4*>(sIn)[i] = v;
        }
        __syncthreads();  // S1: sIn ready; also: all prev-iter gemm2 done (sHid safe to rewrite)

        unsigned long long acc[6][8];
#pragma unroll
        for (int i = 0; i < 6; ++i)
#pragma unroll
            for (int c = 0; c < 8; ++c) acc[i][c] = 0ULL;
        gemm96(sIn, sWa, rg, cgrp, acc);

        // epilogue 1: relu(acc+bias) -> sHid directly (no reg staging)
#pragma unroll
        for (int i = 0; i < 6; ++i) {
            float2 p0 = up2(acc[i][0]), p1 = up2(acc[i][1]), p2 = up2(acc[i][2]), p3 = up2(acc[i][3]);
            float2 p4 = up2(acc[i][4]), p5 = up2(acc[i][5]), p6 = up2(acc[i][6]), p7 = up2(acc[i][7]);
            float4 v0 = make_float4(fmaxf(p0.x + p0.y + ba0.x, 0.f), fmaxf(p1.x + p1.y + ba0.y, 0.f),
                                    fmaxf(p2.x + p2.y + ba0.z, 0.f), fmaxf(p3.x + p3.y + ba0.w, 0.f));
            float4 v1 = make_float4(fmaxf(p4.x + p4.y + ba1.x, 0.f), fmaxf(p5.x + p5.y + ba1.y, 0.f),
                                    fmaxf(p6.x + p6.y + ba1.z, 0.f), fmaxf(p7.x + p7.y + ba1.w, 0.f));
            float4* row = reinterpret_cast<float4*>(sHid + (rg * 6 + i) * 128);
            row[cgrp * 2] = v0;
            row[cgrp * 2 + 1] = v1;
        }
        __syncthreads();  // S2: sHid ready (and all gemm1 sIn reads complete)

#pragma unroll
        for (int i = 0; i < 6; ++i)
#pragma unroll
            for (int c = 0; c < 8; ++c) acc[i][c] = 0ULL;
        gemm96(sHid, sWb, rg, cgrp, acc);

#pragma unroll
        for (int i = 0; i < 6; ++i) {
            int gr = base + rg * 6 + i;
            if (gr < rows) {
                float2 p0 = up2(acc[i][0]), p1 = up2(acc[i][1]), p2 = up2(acc[i][2]), p3 = up2(acc[i][3]);
                float2 p4 = up2(acc[i][4]), p5 = up2(acc[i][5]), p6 = up2(acc[i][6]), p7 = up2(acc[i][7]);
                float4 v0 = make_float4(p0.x + p0.y + bb0.x, p1.x + p1.y + bb0.y,
                                        p2.x + p2.y + bb0.z, p3.x + p3.y + bb0.w);
                float4 v1 = make_float4(p4.x + p4.y + bb1.x, p5.x + p5.y + bb1.y,
                                        p6.x + p6.y + bb1.z, p7.x + p7.y + bb1.w);
                if constexpr (MODE == 0) {
                    int e = g_active[gr];
                    float4* dst = reinterpret_cast<float4*>(g_W + (size_t)e * HH);
                    __stcs(dst + cgrp * 2, v0);
                    __stcs(dst + cgrp * 2 + 1, v1);
                } else {
                    if constexpr (MODE == 1) {
                        v0.x = fmaxf(v0.x, 0.f); v0.y = fmaxf(v0.y, 0.f);
                        v0.z = fmaxf(v0.z, 0.f); v0.w = fmaxf(v0.w, 0.f);
                        v1.x = fmaxf(v1.x, 0.f); v1.y = fmaxf(v1.y, 0.f);
                        v1.z = fmaxf(v1.z, 0.f); v1.w = fmaxf(v1.w, 0.f);
                    }
                    float4 h0 = __ldg(reinterpret_cast<const float4*>(hin) + gr * 32 + cgrp * 2);
                    float4 h1 = __ldg(reinterpret_cast<const float4*>(hin) + gr * 32 + cgrp * 2 + 1);
                    v0.x += h0.x; v0.y += h0.y; v0.z += h0.z; v0.w += h0.w;
                    v1.x += h1.x; v1.y += h1.y; v1.z += h1.z; v1.w += h1.w;
                    reinterpret_cast<float4*>(hout)[gr * 32 + cgrp * 2] = v0;
                    reinterpret_cast<float4*>(hout)[gr * 32 + cgrp * 2 + 1] = v1;
                }
            }
        }
        // next iteration's S1 guards sIn/sHid reuse
    }
}

// ---------------- node embedding: x = relu(z@w0a+b0a)@w0b+b0b (K1=5) ----------------
// smem: sWb 16384 + sHid 12288 + sWa 640 = 29312 floats = 117248 B
#define NODE_EMB_SMEM 117248
__global__ void __launch_bounds__(256, 1) k_node_emb(const float* __restrict__ z,
                                                     const float* __restrict__ w0a,
                                                     const float* __restrict__ b0a,
                                                     const float* __restrict__ w0b,
                                                     const float* __restrict__ b0b) {
    extern __shared__ float sm[];
    float* sWb = sm;             // 16384 (j-split)
    float* sHid = sm + 16384;    // 12288 (96x128)
    float* sWa = sm + 28672;     // 640
    fill_wp(sWb, w0b, threadIdx.x, 256);
    for (int i = threadIdx.x; i < 640; i += 256) sWa[i] = w0a[i];
    __syncthreads();

    const int rg = threadIdx.x >> 4;
    const int cgrp = threadIdx.x & 15;
    const float4 bb0 = reinterpret_cast<const float4*>(b0b)[cgrp * 2];
    const float4 bb1 = reinterpret_cast<const float4*>(b0b)[cgrp * 2 + 1];
    const int ntiles = (NN + TM - 1) / TM;
    for (int t = blockIdx.x; t < ntiles; t += gridDim.x) {
        int base = t * TM;
        for (int i = threadIdx.x; i < TM * 128; i += 256) {
            int r = i >> 7, c = i & 127;
            int gr = base + r;
            float acc = 0.f;
            if (gr < NN) {
#pragma unroll
                for (int k = 0; k < 5; ++k)
                    acc = fmaf(__ldg(z + gr * 5 + k), sWa[k * 128 + c], acc);
                acc = fmaxf(acc + __ldg(b0a + c), 0.f);
            }
            sHid[i] = acc;
        }
        __syncthreads();
        unsigned long long acc[6][8];
#pragma unroll
        for (int i = 0; i < 6; ++i)
#pragma unroll
            for (int c = 0; c < 8; ++c) acc[i][c] = 0ULL;
        gemm96(sHid, sWb, rg, cgrp, acc);
#pragma unroll
        for (int i = 0; i < 6; ++i) {
            int gr = base + rg * 6 + i;
            if (gr < NN) {
                float2 p0 = up2(acc[i][0]), p1 = up2(acc[i][1]), p2 = up2(acc[i][2]), p3 = up2(acc[i][3]);
                float2 p4 = up2(acc[i][4]), p5 = up2(acc[i][5]), p6 = up2(acc[i][6]), p7 = up2(acc[i][7]);
                float4 v0 = make_float4(p0.x + p0.y + bb0.x, p1.x + p1.y + bb0.y,
                                        p2.x + p2.y + bb0.z, p3.x + p3.y + bb0.w);
                float4 v1 = make_float4(p4.x + p4.y + bb1.x, p5.x + p5.y + bb1.y,
                                        p6.x + p6.y + bb1.z, p7.x + p7.y + bb1.w);
                reinterpret_cast<float4*>(g_hA)[gr * 32 + cgrp * 2] = v0;
                reinterpret_cast<float4*>(g_hA)[gr * 32 + cgrp * 2 + 1] = v1;
            }
        }
        __syncthreads();  // sHid reuse guard
    }
}

// ---------------- launch ----------------
extern "C" void kernel_launch(void* const* d_in, const int* in_sizes, int n_in,
                              void* d_out, int out_size) {
    const float* z    = (const float*)d_in[0];
    const int*   ei   = (const int*)d_in[1];
    const float* eatt = (const float*)d_in[2];
    const float* elen = (const float*)d_in[3];
    const float* w0a  = (const float*)d_in[4];
    const float* b0a  = (const float*)d_in[5];
    const float* w0b  = (const float*)d_in[6];
    const float* b0b  = (const float*)d_in[7];
    const float* w1a  = (const float*)d_in[8];
    const float* b1a  = (const float*)d_in[9];
    const float* w1b  = (const float*)d_in[10];
    const float* b1b  = (const float*)d_in[11];
    const float* w2a  = (const float*)d_in[12];
    const float* b2a  = (const float*)d_in[13];
    const float* w2b  = (const float*)d_in[14];
    const float* b2b  = (const float*)d_in[15];
    float* out = (float*)d_out;

    cudaFuncSetAttribute(k_mlp2<0>, cudaFuncAttributeMaxDynamicSharedMemorySize, MLP_SMEM);
    cudaFuncSetAttribute(k_mlp2<1>, cudaFuncAttributeMaxDynamicSharedMemorySize, MLP_SMEM);
    cudaFuncSetAttribute(k_mlp2<2>, cudaFuncAttributeMaxDynamicSharedMemorySize, MLP_SMEM);
    cudaFuncSetAttribute(k_node_emb, cudaFuncAttributeMaxDynamicSharedMemorySize, NODE_EMB_SMEM);

    float *hA, *hB;
    cudaGetSymbolAddress((void**)&hA, g_hA);
    cudaGetSymbolAddress((void**)&hB, g_hB);

    const int ZERO_BLOCKS = (NN * HH / 4) / 256;  // 6250
    const int MSG_BLOCKS  = (EE * 32) / 256;      // 100000

    k_init<<<1, 1>>>();
    k_compact<<<EE / 256, 256>>>(elen);
    k_node_emb<<<148, 256, NODE_EMB_SMEM>>>(z, w0a, b0a, w0b, b0b);
    k_mlp2<0><<<148, 256, MLP_SMEM>>>(eatt, nullptr, w2a, b2a, w2b, b2b, nullptr);

    // conv 0: hA -> hB
    k_zero_agg<<<ZERO_BLOCKS, 256>>>();
    k_message<<<MSG_BLOCKS, 256>>>(ei, hA);
    k_mlp2<1><<<148, 256, MLP_SMEM>>>(nullptr, hA, w1a, b1a, w1b, b1b, hB);

    // conv 1: hB -> hA
    k_zero_agg<<<ZERO_BLOCKS, 256>>>();
    k_message<<<MSG_BLOCKS, 256>>>(ei, hB);
    k_mlp2<1><<<148, 256, MLP_SMEM>>>(nullptr, hB, w1a, b1a, w1b, b1b, hA);

    // conv 2: hA -> out (no inter-layer relu)
    k_zero_agg<<<ZERO_BLOCKS, 256>>>();
    k_message<<<MSG_BLOCKS, 256>>>(ei, hA);
    k_mlp2<2><<<148, 256, MLP_SMEM>>>(nullptr, hA, w1a, b1a, w1b, b1b, out);
}

// round 14
// speedup vs baseline: 1.4028x; 1.0056x over previous
#include <cuda_runtime.h>

#define NN 50000
#define EE 800000
#define HH 128
#define CUTOFF_V 10.0f
#define TM 96   // rows per MLP tile

// ---------------- device scratch (no allocations allowed) ----------------
__device__ float g_W[(size_t)EE * HH];     // edge gate rows (only active rows valid)
__device__ float g_hA[NN * HH];
__device__ float g_hB[NN * HH];
__device__ float g_agg[NN * HH];
__device__ int g_active[EE];
__device__ unsigned char g_mask[EE];
__device__ int g_count;
// CSR (rebuilt every launch; edge_index is conv-invariant within a launch)
__device__ int g_deg[NN];
__device__ int g_rowstart[NN + 1];
__device__ int g_cursor[NN];
__device__ unsigned g_csr[EE];   // bit31 = active flag, bits[0:31) = edge id

// ---------------- f32x2 packed-FMA helpers (Blackwell) ----------------
__device__ __forceinline__ void fma2(unsigned long long& d, unsigned long long a, unsigned long long b) {
    asm("fma.rn.f32x2 %0, %1, %2, %0;" : "+l"(d) : "l"(a), "l"(b));
}
__device__ __forceinline__ float2 up2(unsigned long long v) {
    float2 f;
    asm("mov.b64 {%0, %1}, %2;" : "=f"(f.x), "=f"(f.y) : "l"(v));
    return f;
}

// j-split weight layout: src row-major [128 k][128 c] ->
//   word(k,c) = (k>>1)*256 + ((c>>1)&3)*64 + (c>>3)*4 + (c&1)*2 + (k&1)
// Per (kp, j) the 16 colgroups' 16B fragments are contiguous (256B span)
// -> each warp B-load = 2 conflict-free wavefronts.
__device__ __forceinline__ void fill_wp(float* __restrict__ dst, const float* __restrict__ src,
                                        int tid, int nthr) {
    for (int i = tid; i < 4096; i += nthr) {
        int k = i >> 5, c4 = (i & 31) * 4;
        float4 w = reinterpret_cast<const float4*>(src)[i];
        int kb = (k >> 1) * 256 + (k & 1);
#pragma unroll
        for (int j = 0; j < 4; ++j) {
            int c = c4 + j;
            float val = (j == 0) ? w.x : (j == 1) ? w.y : (j == 2) ? w.z : w.w;
            dst[kb + ((c >> 1) & 3) * 64 + (c >> 3) * 4 + (c & 1) * 2] = val;
        }
    }
}

// 96x128 @ 128x128 GEMM, 256 threads, thread tile 6 rows x 8 cols, K-paired f32x2.
__device__ __forceinline__ void gemm96(const float* __restrict__ sA,
                                       const float* __restrict__ sWp,
                                       int rg, int cgrp, unsigned long long acc[6][8]) {
    const float* a0 = sA + rg * (6 * 128);
    const float* w0 = sWp + cgrp * 4;
#pragma unroll 2
    for (int kp = 0; kp < 64; kp += 2) {   // body = 2 k-pairs = 4 k
        const float* wb = w0 + kp * 256;
        ulonglong2 b00 = *reinterpret_cast<const ulonglong2*>(wb);
        ulonglong2 b01 = *reinterpret_cast<const ulonglong2*>(wb + 64);
        ulonglong2 b02 = *reinterpret_cast<const ulonglong2*>(wb + 128);
        ulonglong2 b03 = *reinterpret_cast<const ulonglong2*>(wb + 192);
        ulonglong2 b10 = *reinterpret_cast<const ulonglong2*>(wb + 256);
        ulonglong2 b11 = *reinterpret_cast<const ulonglong2*>(wb + 320);
        ulonglong2 b12 = *reinterpret_cast<const ulonglong2*>(wb + 384);
        ulonglong2 b13 = *reinterpret_cast<const ulonglong2*>(wb + 448);
#pragma unroll
        for (int i = 0; i < 6; ++i) {
            ulonglong2 ap = *reinterpret_cast<const ulonglong2*>(a0 + i * 128 + kp * 2);
            fma2(acc[i][0], ap.x, b00.x); fma2(acc[i][1], ap.x, b00.y);
            fma2(acc[i][2], ap.x, b01.x); fma2(acc[i][3], ap.x, b01.y);
            fma2(acc[i][4], ap.x, b02.x); fma2(acc[i][5], ap.x, b02.y);
            fma2(acc[i][6], ap.x, b03.x); fma2(acc[i][7], ap.x, b03.y);
            fma2(acc[i][0], ap.y, b10.x); fma2(acc[i][1], ap.y, b10.y);
            fma2(acc[i][2], ap.y, b11.x); fma2(acc[i][3], ap.y, b11.y);
            fma2(acc[i][4], ap.y, b12.x); fma2(acc[i][5], ap.y, b12.y);
            fma2(acc[i][6], ap.y, b13.x); fma2(acc[i][7], ap.y, b13.y);
        }
    }
}

// ---------------- CSR build ----------------
__global__ void __launch_bounds__(256) k_init() {
    int i = blockIdx.x * 256 + threadIdx.x;   // grid covers NN
    if (i < NN) g_deg[i] = 0;
    if (i == 0) g_count = 0;
}

// mask + active-list compaction + degree histogram
__global__ void __launch_bounds__(256) k_compact(const float* __restrict__ elen,
                                                 const int* __restrict__ ei) {
    int e = blockIdx.x * 256 + threadIdx.x;
    int lane = threadIdx.x & 31;
    bool a = (elen[e] <= CUTOFF_V);
    g_mask[e] = a ? (unsigned char)1 : (unsigned char)0;
    unsigned m = __ballot_sync(0xffffffffu, a);
    int cnt = __popc(m);
    int base = 0;
    if (lane == 0 && cnt) base = atomicAdd(&g_count, cnt);
    base = __shfl_sync(0xffffffffu, base, 0);
    if (a) {
        int off = __popc(m & ((1u << lane) - 1u));
        g_active[base + off] = e;
    }
    atomicAdd(&g_deg[__ldg(ei + EE + e)], 1);
}

// single-block exclusive scan over g_deg -> g_rowstart, g_cursor
__global__ void __launch_bounds__(1024) k_scan() {
    __shared__ int part[1024];
    const int CH = (NN + 1023) / 1024;  // 49
    int t = threadIdx.x;
    int beg = t * CH, end = beg + CH < NN ? beg + CH : NN;
    int s = 0;
    for (int i = beg; i < end; ++i) s += g_deg[i];
    part[t] = s;
    __syncthreads();
    for (int off = 1; off < 1024; off <<= 1) {
        int v = (t >= off) ? part[t - off] : 0;
        __syncthreads();
        part[t] += v;
        __syncthreads();
    }
    int run = (t == 0) ? 0 : part[t - 1];
    for (int i = beg; i < end; ++i) {
        g_rowstart[i] = run;
        g_cursor[i] = run;
        run += g_deg[i];
    }
    if (t == 1023) g_rowstart[NN] = part[1023];
}

__global__ void __launch_bounds__(256) k_scatter(const int* __restrict__ ei) {
    int e = blockIdx.x * 256 + threadIdx.x;
    int d = __ldg(ei + EE + e);
    int pos = atomicAdd(&g_cursor[d], 1);
    g_csr[pos] = (unsigned)e | ((unsigned)g_mask[e] << 31);
}

// ---------------- aggregation: one warp per dst node, no atomics ----------------
__global__ void __launch_bounds__(256) k_agg(const int* __restrict__ ei,
                                             const float* __restrict__ hin) {
    int gw = (blockIdx.x * 256 + threadIdx.x) >> 5;   // dst node (grid = exactly NN warps)
    if (gw >= NN) return;
    int lane = threadIdx.x & 31;
    int p0 = g_rowstart[gw], p1 = g_rowstart[gw + 1];
    float4 acc = make_float4(0.f, 0.f, 0.f, 0.f);
    for (int p = p0; p < p1; ++p) {
        unsigned v = g_csr[p];                        // warp-uniform broadcast
        int e = (int)(v & 0x7fffffffu);
        int src = __ldg(ei + e);
        float4 m = __ldg(reinterpret_cast<const float4*>(hin) + src * 32 + lane);
        if (v >> 31) {
            float4 wv = __ldcs(reinterpret_cast<const float4*>(g_W + (size_t)e * HH) + lane);
            m.x += wv.x; m.y += wv.y; m.z += wv.z; m.w += wv.w;
        }
        acc.x += fmaxf(m.x, 0.f); acc.y += fmaxf(m.y, 0.f);
        acc.z += fmaxf(m.z, 0.f); acc.w += fmaxf(m.w, 0.f);
    }
    reinterpret_cast<float4*>(g_agg)[gw * 32 + lane] = acc;
}

// ---------------- fused 2-layer MLP: 256 threads, 96-row tiles, 6x8 tile ----------------
// smem: sWa 16384 + sWb 16384 + sIn 12288 + sHid 12288 = 57344 floats = 229376 B
#define MLP_SMEM 229376
// MODE 0: edge gate  : rows = g_count (compacted), in = edge_attr[g_active[r]], out = g_W[e]
// MODE 1: node update: in = g_agg + hin, out = relu(mlp(in)) + hin
// MODE 2: node update: in = g_agg + hin, out = mlp(in) + hin   (last conv)
template <int MODE>
__global__ void __launch_bounds__(256, 1) k_mlp2(const float* __restrict__ inp,
                                                 const float* __restrict__ hin,
                                                 const float* __restrict__ wa,
                                                 const float* __restrict__ ba,
                                                 const float* __restrict__ wb,
                                                 const float* __restrict__ bb,
                                                 float* __restrict__ hout) {
    extern __shared__ float sm[];
    float* sWa = sm;             // 16384 (j-split)
    float* sWb = sm + 16384;     // 16384 (j-split)
    float* sIn = sm + 32768;     // 12288 (row-major 96x128)
    float* sHid = sm + 45056;    // 12288 (row-major 96x128)

    fill_wp(sWa, wa, threadIdx.x, 256);
    fill_wp(sWb, wb, threadIdx.x, 256);
    __syncthreads();

    const int rows = (MODE == 0) ? g_count : NN;
    const int ntiles = (rows + TM - 1) / TM;
    const int rg = threadIdx.x >> 4;      // 0..15: rows rg*6..rg*6+5
    const int cgrp = threadIdx.x & 15;    // cols cgrp*8..cgrp*8+7
    const float4 ba0 = reinterpret_cast<const float4*>(ba)[cgrp * 2];
    const float4 ba1 = reinterpret_cast<const float4*>(ba)[cgrp * 2 + 1];
    const float4 bb0 = reinterpret_cast<const float4*>(bb)[cgrp * 2];
    const float4 bb1 = reinterpret_cast<const float4*>(bb)[cgrp * 2 + 1];

    for (int t = blockIdx.x; t < ntiles; t += gridDim.x) {
        const int base = t * TM;
        for (int i = threadIdx.x; i < 3072; i += 256) {
            int r = i >> 5, c4 = i & 31;
            int gr = base + r;
            float4 v = make_float4(0.f, 0.f, 0.f, 0.f);
            if (gr < rows) {
                if constexpr (MODE == 0) {
                    int e = g_active[gr];
                    v = __ldcs(reinterpret_cast<const float4*>(inp + (size_t)e * HH) + c4);
                } else {
                    float4 x = reinterpret_cast<const float4*>(g_agg)[gr * 32 + c4];
                    float4 y = __ldg(reinterpret_cast<const float4*>(hin) + gr * 32 + c4);
                    v = make_float4(x.x + y.x, x.y + y.y, x.z + y.z, x.w + y.w);
                }
            }
            reinterpret_cast<float4*>(sIn)[i] = v;
        }
        __syncthreads();  // S1: sIn ready; prev-iter gemm2 done (sHid safe)

        unsigned long long acc[6][8];
#pragma unroll
        for (int i = 0; i < 6; ++i)
#pragma unroll
            for (int c = 0; c < 8; ++c) acc[i][c] = 0ULL;
        gemm96(sIn, sWa, rg, cgrp, acc);

#pragma unroll
        for (int i = 0; i < 6; ++i) {
            float2 p0 = up2(acc[i][0]), p1 = up2(acc[i][1]), p2 = up2(acc[i][2]), p3 = up2(acc[i][3]);
            float2 p4 = up2(acc[i][4]), p5 = up2(acc[i][5]), p6 = up2(acc[i][6]), p7 = up2(acc[i][7]);
            float4 v0 = make_float4(fmaxf(p0.x + p0.y + ba0.x, 0.f), fmaxf(p1.x + p1.y + ba0.y, 0.f),
                                    fmaxf(p2.x + p2.y + ba0.z, 0.f), fmaxf(p3.x + p3.y + ba0.w, 0.f));
            float4 v1 = make_float4(fmaxf(p4.x + p4.y + ba1.x, 0.f), fmaxf(p5.x + p5.y + ba1.y, 0.f),
                                    fmaxf(p6.x + p6.y + ba1.z, 0.f), fmaxf(p7.x + p7.y + ba1.w, 0.f));
            float4* row = reinterpret_cast<float4*>(sHid + (rg * 6 + i) * 128);
            row[cgrp * 2] = v0;
            row[cgrp * 2 + 1] = v1;
        }
        __syncthreads();  // S2: sHid ready (gemm1 sIn reads complete)

#pragma unroll
        for (int i = 0; i < 6; ++i)
#pragma unroll
            for (int c = 0; c < 8; ++c) acc[i][c] = 0ULL;
        gemm96(sHid, sWb, rg, cgrp, acc);

#pragma unroll
        for (int i = 0; i < 6; ++i) {
            int gr = base + rg * 6 + i;
            if (gr < rows) {
                float2 p0 = up2(acc[i][0]), p1 = up2(acc[i][1]), p2 = up2(acc[i][2]), p3 = up2(acc[i][3]);
                float2 p4 = up2(acc[i][4]), p5 = up2(acc[i][5]), p6 = up2(acc[i][6]), p7 = up2(acc[i][7]);
                float4 v0 = make_float4(p0.x + p0.y + bb0.x, p1.x + p1.y + bb0.y,
                                        p2.x + p2.y + bb0.z, p3.x + p3.y + bb0.w);
                float4 v1 = make_float4(p4.x + p4.y + bb1.x, p5.x + p5.y + bb1.y,
                                        p6.x + p6.y + bb1.z, p7.x + p7.y + bb1.w);
                if constexpr (MODE == 0) {
                    int e = g_active[gr];
                    float4* dst = reinterpret_cast<float4*>(g_W + (size_t)e * HH);
                    __stcs(dst + cgrp * 2, v0);
                    __stcs(dst + cgrp * 2 + 1, v1);
                } else {
                    if constexpr (MODE == 1) {
                        v0.x = fmaxf(v0.x, 0.f); v0.y = fmaxf(v0.y, 0.f);
                        v0.z = fmaxf(v0.z, 0.f); v0.w = fmaxf(v0.w, 0.f);
                        v1.x = fmaxf(v1.x, 0.f); v1.y = fmaxf(v1.y, 0.f);
                        v1.z = fmaxf(v1.z, 0.f); v1.w = fmaxf(v1.w, 0.f);
                    }
                    float4 h0 = __ldg(reinterpret_cast<const float4*>(hin) + gr * 32 + cgrp * 2);
                    float4 h1 = __ldg(reinterpret_cast<const float4*>(hin) + gr * 32 + cgrp * 2 + 1);
                    v0.x += h0.x; v0.y += h0.y; v0.z += h0.z; v0.w += h0.w;
                    v1.x += h1.x; v1.y += h1.y; v1.z += h1.z; v1.w += h1.w;
                    reinterpret_cast<float4*>(hout)[gr * 32 + cgrp * 2] = v0;
                    reinterpret_cast<float4*>(hout)[gr * 32 + cgrp * 2 + 1] = v1;
                }
            }
        }
        // next iteration's S1 guards sIn/sHid reuse
    }
}

// ---------------- node embedding: x = relu(z@w0a+b0a)@w0b+b0b (K1=5) ----------------
// smem: sWb 16384 + sHid 12288 + sWa 640 = 29312 floats = 117248 B
#define NODE_EMB_SMEM 117248
__global__ void __launch_bounds__(256, 1) k_node_emb(const float* __restrict__ z,
                                                     const float* __restrict__ w0a,
                                                     const float* __restrict__ b0a,
                                                     const float* __restrict__ w0b,
                                                     const float* __restrict__ b0b) {
    extern __shared__ float sm[];
    float* sWb = sm;             // 16384 (j-split)
    float* sHid = sm + 16384;    // 12288 (96x128)
    float* sWa = sm + 28672;     // 640
    fill_wp(sWb, w0b, threadIdx.x, 256);
    for (int i = threadIdx.x; i < 640; i += 256) sWa[i] = w0a[i];
    __syncthreads();

    const int rg = threadIdx.x >> 4;
    const int cgrp = threadIdx.x & 15;
    const float4 bb0 = reinterpret_cast<const float4*>(b0b)[cgrp * 2];
    const float4 bb1 = reinterpret_cast<const float4*>(b0b)[cgrp * 2 + 1];
    const int ntiles = (NN + TM - 1) / TM;
    for (int t = blockIdx.x; t < ntiles; t += gridDim.x) {
        int base = t * TM;
        for (int i = threadIdx.x; i < TM * 128; i += 256) {
            int r = i >> 7, c = i & 127;
            int gr = base + r;
            float acc = 0.f;
            if (gr < NN) {
#pragma unroll
                for (int k = 0; k < 5; ++k)
                    acc = fmaf(__ldg(z + gr * 5 + k), sWa[k * 128 + c], acc);
                acc = fmaxf(acc + __ldg(b0a + c), 0.f);
            }
            sHid[i] = acc;
        }
        __syncthreads();
        unsigned long long acc[6][8];
#pragma unroll
        for (int i = 0; i < 6; ++i)
#pragma unroll
            for (int c = 0; c < 8; ++c) acc[i][c] = 0ULL;
        gemm96(sHid, sWb, rg, cgrp, acc);
#pragma unroll
        for (int i = 0; i < 6; ++i) {
            int gr = base + rg * 6 + i;
            if (gr < NN) {
                float2 p0 = up2(acc[i][0]), p1 = up2(acc[i][1]), p2 = up2(acc[i][2]), p3 = up2(acc[i][3]);
                float2 p4 = up2(acc[i][4]), p5 = up2(acc[i][5]), p6 = up2(acc[i][6]), p7 = up2(acc[i][7]);
                float4 v0 = make_float4(p0.x + p0.y + bb0.x, p1.x + p1.y + bb0.y,
                                        p2.x + p2.y + bb0.z, p3.x + p3.y + bb0.w);
                float4 v1 = make_float4(p4.x + p4.y + bb1.x, p5.x + p5.y + bb1.y,
                                        p6.x + p6.y + bb1.z, p7.x + p7.y + bb1.w);
                reinterpret_cast<float4*>(g_hA)[gr * 32 + cgrp * 2] = v0;
                reinterpret_cast<float4*>(g_hA)[gr * 32 + cgrp * 2 + 1] = v1;
            }
        }
        __syncthreads();  // sHid reuse guard
    }
}

// ---------------- launch ----------------
extern "C" void kernel_launch(void* const* d_in, const int* in_sizes, int n_in,
                              void* d_out, int out_size) {
    const float* z    = (const float*)d_in[0];
    const int*   ei   = (const int*)d_in[1];
    const float* eatt = (const float*)d_in[2];
    const float* elen = (const float*)d_in[3];
    const float* w0a  = (const float*)d_in[4];
    const float* b0a  = (const float*)d_in[5];
    const float* w0b  = (const float*)d_in[6];
    const float* b0b  = (const float*)d_in[7];
    const float* w1a  = (const float*)d_in[8];
    const float* b1a  = (const float*)d_in[9];
    const float* w1b  = (const float*)d_in[10];
    const float* b1b  = (const float*)d_in[11];
    const float* w2a  = (const float*)d_in[12];
    const float* b2a  = (const float*)d_in[13];
    const float* w2b  = (const float*)d_in[14];
    const float* b2b  = (const float*)d_in[15];
    float* out = (float*)d_out;

    cudaFuncSetAttribute(k_mlp2<0>, cudaFuncAttributeMaxDynamicSharedMemorySize, MLP_SMEM);
    cudaFuncSetAttribute(k_mlp2<1>, cudaFuncAttributeMaxDynamicSharedMemorySize, MLP_SMEM);
    cudaFuncSetAttribute(k_mlp2<2>, cudaFuncAttributeMaxDynamicSharedMemorySize, MLP_SMEM);
    cudaFuncSetAttribute(k_node_emb, cudaFuncAttributeMaxDynamicSharedMemorySize, NODE_EMB_SMEM);

    float *hA, *hB;
    cudaGetSymbolAddress((void**)&hA, g_hA);
    cudaGetSymbolAddress((void**)&hB, g_hB);

    const int AGG_BLOCKS = (NN * 32 + 255) / 256;  // 6250 (one warp per node)

    // CSR build (edge structure is launch-invariant across the 3 convs)
    k_init<<<(NN + 255) / 256, 256>>>();
    k_compact<<<EE / 256, 256>>>(elen, ei);
    k_scan<<<1, 1024>>>();
    k_scatter<<<EE / 256, 256>>>(ei);

    k_node_emb<<<148, 256, NODE_EMB_SMEM>>>(z, w0a, b0a, w0b, b0b);
    k_mlp2<0><<<148, 256, MLP_SMEM>>>(eatt, nullptr, w2a, b2a, w2b, b2b, nullptr);

    // conv 0: hA -> hB
    k_agg<<<AGG_BLOCKS, 256>>>(ei, hA);
    k_mlp2<1><<<148, 256, MLP_SMEM>>>(nullptr, hA, w1a, b1a, w1b, b1b, hB);

    // conv 1: hB -> hA
    k_agg<<<AGG_BLOCKS, 256>>>(ei, hB);
    k_mlp2<1><<<148, 256, MLP_SMEM>>>(nullptr, hB, w1a, b1a, w1b, b1b, hA);

    // conv 2: hA -> out (no inter-layer relu)
    k_agg<<<AGG_BLOCKS, 256>>>(ei, hA);
    k_mlp2<2><<<148, 256, MLP_SMEM>>>(nullptr, hA, w1a, b1a, w1b, b1b, out);
}